// round 11
// baseline (speedup 1.0000x reference)
#include <cuda_runtime.h>
#include <cstdint>

#define NUM_KEYS  1000000
#define NUM_NODES 100000
#define LP   4
#define ENC  32
#define FEAT 64
#define D3   64

// ---------------- device-global scratch ----------------
__device__ __align__(16) float g_featc[(size_t)NUM_NODES * D3];  // feat@Wm1b + bm1 + b2@Wm1a
__device__ __align__(16) float g_wfused[ENC * D3];               // W2 @ Wm1[:32]

// ---------------- constant weights (warp-uniform -> LDCU port) ----------------
__constant__ __align__(16) float4 cWf4[ENC * D3 / 4];     // Wfused [j][16 float4]
__constant__ __align__(16) float4 cWm1b4[FEAT * D3 / 4];  // Wm1 bottom half [k][16 float4]
__constant__ float cW1[LP * ENC];                          // raw [4][32]
__constant__ float cb1[ENC];
__constant__ float cWm2[D3];
__constant__ float cbm2[1];

// ---------------- f32x2 helpers ----------------
__device__ __forceinline__ unsigned long long pk2(float a, float b) {
    unsigned long long r;
    asm("mov.b64 %0, {%1, %2};" : "=l"(r) : "f"(a), "f"(b));
    return r;
}
__device__ __forceinline__ void upk2(unsigned long long v, float& a, float& b) {
    asm("mov.b64 {%0, %1}, %2;" : "=f"(a), "=f"(b) : "l"(v));
}
__device__ __forceinline__ unsigned long long fma2(unsigned long long a, unsigned long long b,
                                                   unsigned long long c) {
    unsigned long long d;
    asm("fma.rn.f32x2 %0, %1, %2, %3;" : "=l"(d) : "l"(a), "l"(b), "l"(c));
    return d;
}

// ---------------- fold kernel: g_wfused = W2 @ Wm1[:32] ----------------
__global__ void fold_weights_kernel(const float* __restrict__ W2,
                                    const float* __restrict__ Wm1) {
    int p = blockIdx.x * 256 + threadIdx.x;   // < 2048
    int j = p >> 6, d = p & 63;
    float s = 0.f;
#pragma unroll
    for (int c = 0; c < ENC; c++) s = fmaf(W2[j * ENC + c], Wm1[c * D3 + d], s);
    g_wfused[p] = s;
}

// ---------------- per-node precompute ----------------
// g_featc[n][d] = (bm1[d] + b2@Wm1[:32][:,d]) + node_feat[n] @ Wm1[32:][:,d]
// 64 nodes/block; warp w owns output cols [8w, 8w+8); lane owns rows lane & lane+32.
__global__ __launch_bounds__(256) void node_precompute_kernel(
    const float* __restrict__ node_feat,
    const float* __restrict__ Wm1,
    const float* __restrict__ b2,
    const float* __restrict__ bm1) {
    __shared__ float sFT[FEAT * 65];   // transposed feats [k][row], stride 65
    __shared__ float sc[D3];

    int t = threadIdx.x;
    int n0 = blockIdx.x * 64;

    if (t < D3) {
        float s = bm1[t];
#pragma unroll
        for (int c = 0; c < ENC; c++) s = fmaf(b2[c], Wm1[c * D3 + t], s);
        sc[t] = s;
    }
    for (int i = t; i < 64 * FEAT; i += 256) {
        int r = i >> 6, k = i & 63;
        int n = n0 + r;
        sFT[k * 65 + r] = (n < NUM_NODES) ? node_feat[(size_t)n * FEAT + k] : 0.f;
    }
    __syncthreads();

    int w = t >> 5, lane = t & 31;
    int c0 = w * 8;          // 8 output cols per warp (uniform)
    int cw = w * 2;          // float4 index base (uniform)

#pragma unroll
    for (int half = 0; half < 2; half++) {
        int r = half * 32 + lane;
        unsigned long long acc0 = pk2(sc[c0], sc[c0 + 1]);
        unsigned long long acc1 = pk2(sc[c0 + 2], sc[c0 + 3]);
        unsigned long long acc2 = pk2(sc[c0 + 4], sc[c0 + 5]);
        unsigned long long acc3 = pk2(sc[c0 + 6], sc[c0 + 7]);
#pragma unroll
        for (int k = 0; k < FEAT; k++) {
            float f = sFT[k * 65 + r];
            unsigned long long ff = pk2(f, f);
            float4 w0 = cWm1b4[k * 16 + cw];
            float4 w1 = cWm1b4[k * 16 + cw + 1];
            acc0 = fma2(ff, pk2(w0.x, w0.y), acc0);
            acc1 = fma2(ff, pk2(w0.z, w0.w), acc1);
            acc2 = fma2(ff, pk2(w1.x, w1.y), acc2);
            acc3 = fma2(ff, pk2(w1.z, w1.w), acc3);
        }
        int n = n0 + r;
        if (n < NUM_NODES) {
            float a, b, c, d;
            upk2(acc0, a, b); upk2(acc1, c, d);
            *((float4*)&g_featc[(size_t)n * D3 + c0]) = make_float4(a, b, c, d);
            upk2(acc2, a, b); upk2(acc3, c, d);
            *((float4*)&g_featc[(size_t)n * D3 + c0 + 4]) = make_float4(a, b, c, d);
        }
    }
}

// ---------------- main fused kernel ----------------
// dynamic smem: [0,1024) sNod int[256]; [1024, 1024+256*66*4) sbuf staged featc
#define RSTR 66
#define SMEM_BYTES (1024 + 256 * RSTR * 4)

__global__ __launch_bounds__(256, 3) void main_kernel(
    const float* __restrict__ pos_table,
    const int* __restrict__ key_idx,
    const int* __restrict__ node_idx,
    float* __restrict__ out, int total) {
    extern __shared__ char smemraw[];
    int*   sNod = (int*)smemraw;
    float* sbuf = (float*)(smemraw + 1024);

    int t = threadIdx.x;
    int e = blockIdx.x * 256 + t;
    int ec = e < total ? e : total - 1;

    int k = __ldg(key_idx + ec);
    sNod[t] = __ldg(node_idx + ec);
    float4 enc = __ldg(((const float4*)pos_table) + k);
    __syncthreads();

    // ---- coalesced cooperative stage of 256 featc rows ----
    const float4* gfc = (const float4*)g_featc;
#pragma unroll
    for (int i = 0; i < 16; i++) {
        int c = t + 256 * i;        // 0..4095
        int r = c >> 4;             // row 0..255
        int q = c & 15;             // float4 chunk within row
        int rn = sNod[r];
        float4 v = __ldg(gfc + (size_t)rn * 16 + q);
        float2* dst = (float2*)&sbuf[r * RSTR + q * 4];
        dst[0] = make_float2(v.x, v.y);
        dst[1] = make_float2(v.z, v.w);
    }
    __syncthreads();

    // h accumulators from own staged row (LDS.64, max 2-way conflict)
    unsigned long long h[D3 / 2];
    {
        const float2* myrow = (const float2*)&sbuf[t * RSTR];
#pragma unroll
        for (int p = 0; p < D3 / 2; p++) {
            float2 v = myrow[p];
            h[p] = pk2(v.x, v.y);
        }
    }

    // j-loop: all weights via constant (LDCU), zero shared traffic
#pragma unroll
    for (int j = 0; j < ENC; j++) {
        float aj = cb1[j];
        aj = fmaf(enc.x, cW1[j],           aj);
        aj = fmaf(enc.y, cW1[ENC + j],     aj);
        aj = fmaf(enc.z, cW1[2 * ENC + j], aj);
        aj = fmaf(enc.w, cW1[3 * ENC + j], aj);
        aj = fmaxf(aj, 0.0f);
        unsigned long long aa = pk2(aj, aj);
#pragma unroll
        for (int q = 0; q < 16; q++) {
            float4 wv = cWf4[j * 16 + q];
            h[2 * q]     = fma2(aa, pk2(wv.x, wv.y), h[2 * q]);
            h[2 * q + 1] = fma2(aa, pk2(wv.z, wv.w), h[2 * q + 1]);
        }
    }

    float z = cbm2[0];
#pragma unroll
    for (int p = 0; p < D3 / 2; p++) {
        float x, y;
        upk2(h[p], x, y);
        z = fmaf(fmaxf(x, 0.0f), cWm2[2 * p],     z);
        z = fmaf(fmaxf(y, 0.0f), cWm2[2 * p + 1], z);
    }
    if (e < total) out[e] = z;
}

// ---------------- launch ----------------
extern "C" void kernel_launch(void* const* d_in, const int* in_sizes, int n_in,
                              void* d_out, int out_size) {
    const float* pos_table = (const float*)d_in[0];
    const float* node_feat = (const float*)d_in[1];
    const float* W1  = (const float*)d_in[2];
    const float* b1  = (const float*)d_in[3];
    const float* W2  = (const float*)d_in[4];
    const float* b2  = (const float*)d_in[5];
    const float* Wm1 = (const float*)d_in[6];
    const float* bm1 = (const float*)d_in[7];
    const float* Wm2 = (const float*)d_in[8];
    const float* bm2 = (const float*)d_in[9];
    const int* key_idx  = (const int*)d_in[10];
    const int* node_idx = (const int*)d_in[11];
    float* out = (float*)d_out;

    static void* g_wfused_ptr = nullptr;
    static bool init_done = false;
    if (!init_done) {
        cudaFuncSetAttribute(main_kernel, cudaFuncAttributeMaxDynamicSharedMemorySize, SMEM_BYTES);
        cudaGetSymbolAddress(&g_wfused_ptr, g_wfused);
        init_done = true;
    }

    // small weights straight into constant (D2D async memcpys: graph-legal)
    cudaMemcpyToSymbolAsync(cWm1b4, Wm1 + ENC * D3, FEAT * D3 * sizeof(float), 0,
                            cudaMemcpyDeviceToDevice, 0);
    cudaMemcpyToSymbolAsync(cW1,  W1,  LP * ENC * sizeof(float), 0, cudaMemcpyDeviceToDevice, 0);
    cudaMemcpyToSymbolAsync(cb1,  b1,  ENC * sizeof(float),      0, cudaMemcpyDeviceToDevice, 0);
    cudaMemcpyToSymbolAsync(cWm2, Wm2, D3 * sizeof(float),       0, cudaMemcpyDeviceToDevice, 0);
    cudaMemcpyToSymbolAsync(cbm2, bm2, sizeof(float),            0, cudaMemcpyDeviceToDevice, 0);

    // fold Wfused on device, then copy into constant
    fold_weights_kernel<<<8, 256>>>(W2, Wm1);
    cudaMemcpyToSymbolAsync(cWf4, g_wfused_ptr, ENC * D3 * sizeof(float), 0,
                            cudaMemcpyDeviceToDevice, 0);

    node_precompute_kernel<<<(NUM_NODES + 63) / 64, 256>>>(node_feat, Wm1, b2, bm1);

    int total = out_size;
    main_kernel<<<(total + 255) / 256, 256, SMEM_BYTES>>>(pos_table, key_idx, node_idx, out, total);
}